// round 1
// baseline (speedup 1.0000x reference)
#include <cuda_runtime.h>
#include <cuda_bf16.h>
#include <math.h>

#define N 2048
#define K 4096

// ---------------- device scratch (no allocations allowed) ----------------
__device__ float              g_D[(size_t)N * N];   // 16 MB distance matrix
__device__ float              g_sq[N];
__device__ int                g_comp[N];
__device__ int                g_parent[N];
__device__ unsigned long long g_minEdge[N];
__device__ float              g_edgeW[N];
__device__ int                g_cnt;

// ---------------- 1) row squared norms ----------------
__global__ void sq_kernel(const float* __restrict__ x) {
    int row = blockIdx.x;
    int tid = threadIdx.x;
    const float4* xr = (const float4*)(x + (size_t)row * K);
    float s = 0.f;
    #pragma unroll 4
    for (int i = tid; i < K / 4; i += 128) {
        float4 v = xr[i];
        s += v.x * v.x + v.y * v.y + v.z * v.z + v.w * v.w;
    }
    // warp reduce
    for (int o = 16; o > 0; o >>= 1) s += __shfl_down_sync(0xffffffffu, s, o);
    __shared__ float ws[4];
    if ((tid & 31) == 0) ws[tid >> 5] = s;
    __syncthreads();
    if (tid == 0) g_sq[row] = ws[0] + ws[1] + ws[2] + ws[3];
}

// ---------------- 2) GEMM (X X^T) fused with distance epilogue ----------------
// BM=BN=128, BK=8, 256 threads, 8x8 per thread, register prefetch.
__global__ __launch_bounds__(256) void gemm_dist_kernel(const float* __restrict__ X) {
    __shared__ float As[8][128];
    __shared__ float Bs[8][128];

    const int m0 = blockIdx.y * 128;
    const int n0 = blockIdx.x * 128;
    const int t  = threadIdx.x;

    const int lrow = t >> 1;           // 0..127
    const int lcol = (t & 1) << 2;     // 0 or 4

    const int tr = t >> 4;             // 0..15
    const int tc = t & 15;             // 0..15
    const int rowBase = tr * 8;
    const int colBase = tc * 8;

    const float* Abase = X + (size_t)(m0 + lrow) * K + lcol;
    const float* Bbase = X + (size_t)(n0 + lrow) * K + lcol;

    float acc[8][8];
    #pragma unroll
    for (int i = 0; i < 8; i++)
        #pragma unroll
        for (int j = 0; j < 8; j++) acc[i][j] = 0.f;

    // preload tile 0
    float4 ra = *(const float4*)(Abase);
    float4 rb = *(const float4*)(Bbase);
    As[lcol + 0][lrow] = ra.x; As[lcol + 1][lrow] = ra.y;
    As[lcol + 2][lrow] = ra.z; As[lcol + 3][lrow] = ra.w;
    Bs[lcol + 0][lrow] = rb.x; Bs[lcol + 1][lrow] = rb.y;
    Bs[lcol + 2][lrow] = rb.z; Bs[lcol + 3][lrow] = rb.w;
    __syncthreads();

    for (int k0 = 8; k0 <= K; k0 += 8) {
        float4 na, nb;
        if (k0 < K) {
            na = *(const float4*)(Abase + k0);
            nb = *(const float4*)(Bbase + k0);
        }
        #pragma unroll
        for (int kk = 0; kk < 8; kk++) {
            float a[8], b[8];
            #pragma unroll
            for (int i = 0; i < 8; i++) a[i] = As[kk][rowBase + i];
            #pragma unroll
            for (int j = 0; j < 8; j++) b[j] = Bs[kk][colBase + j];
            #pragma unroll
            for (int i = 0; i < 8; i++)
                #pragma unroll
                for (int j = 0; j < 8; j++)
                    acc[i][j] = fmaf(a[i], b[j], acc[i][j]);
        }
        if (k0 < K) {
            __syncthreads();
            As[lcol + 0][lrow] = na.x; As[lcol + 1][lrow] = na.y;
            As[lcol + 2][lrow] = na.z; As[lcol + 3][lrow] = na.w;
            Bs[lcol + 0][lrow] = nb.x; Bs[lcol + 1][lrow] = nb.y;
            Bs[lcol + 2][lrow] = nb.z; Bs[lcol + 3][lrow] = nb.w;
            __syncthreads();
        }
    }

    // epilogue: D = sqrt(max(sq_i + sq_j - 2*g, 0))
    float si[8], sj[8];
    #pragma unroll
    for (int i = 0; i < 8; i++) si[i] = g_sq[m0 + rowBase + i];
    #pragma unroll
    for (int j = 0; j < 8; j++) sj[j] = g_sq[n0 + colBase + j];

    #pragma unroll
    for (int i = 0; i < 8; i++) {
        float4 o0, o1;
        float* row = g_D + (size_t)(m0 + rowBase + i) * N + (n0 + colBase);
        float d[8];
        #pragma unroll
        for (int j = 0; j < 8; j++) {
            float d2 = si[i] + sj[j] - 2.f * acc[i][j];
            d[j] = sqrtf(fmaxf(d2, 0.f));
        }
        o0.x = d[0]; o0.y = d[1]; o0.z = d[2]; o0.w = d[3];
        o1.x = d[4]; o1.y = d[5]; o1.z = d[6]; o1.w = d[7];
        *(float4*)(row)     = o0;
        *(float4*)(row + 4) = o1;
    }
}

// ---------------- 3) Boruvka MST ----------------
__global__ void init_kernel() {
    int i = blockIdx.x * blockDim.x + threadIdx.x;
    if (i < N) g_comp[i] = i;
    if (i == 0) g_cnt = 0;
}

__global__ void reset_kernel() {
    int i = blockIdx.x * blockDim.x + threadIdx.x;
    if (i < N) {
        g_minEdge[i] = ~0ull;
        g_parent[i]  = i;
    }
}

// one block per vertex: min outgoing edge -> atomicMin into component slot
__global__ void scan_kernel() {
    int v   = blockIdx.x;
    int tid = threadIdx.x;
    int cv  = g_comp[v];
    const float* __restrict__ row = g_D + (size_t)v * N;

    unsigned long long best = ~0ull;
    for (int j = tid; j < N; j += 256) {
        if (g_comp[j] != cv) {
            float w = row[j];
            unsigned int p = (v < j) ? (unsigned)(v * N + j) : (unsigned)(j * N + v);
            unsigned long long key = ((unsigned long long)__float_as_uint(w) << 32) | p;
            best = min(best, key);
        }
    }
    __shared__ unsigned long long sm[256];
    sm[tid] = best;
    __syncthreads();
    for (int s = 128; s > 0; s >>= 1) {
        if (tid < s) sm[tid] = min(sm[tid], sm[tid + s]);
        __syncthreads();
    }
    if (tid == 0 && sm[0] != ~0ull) atomicMin(&g_minEdge[cv], sm[0]);
}

__global__ void merge_kernel() {
    int c = blockIdx.x * blockDim.x + threadIdx.x;
    if (c >= N || g_comp[c] != c) return;
    unsigned long long key = g_minEdge[c];
    if (key == ~0ull) return;

    unsigned int p = (unsigned int)key;
    int a = p / N, b = p % N;
    int ra = g_comp[a], rb = g_comp[b];
    int rd = (ra == c) ? rb : ra;

    // mutual-pair symmetry break: only the smaller root merges
    bool skip = false;
    unsigned long long key2 = g_minEdge[rd];
    if (key2 != ~0ull) {
        unsigned int p2 = (unsigned int)key2;
        int a2 = p2 / N, b2 = p2 % N;
        int ra2 = g_comp[a2], rb2 = g_comp[b2];
        int tgt = (ra2 == rd) ? rb2 : ra2;
        if (tgt == c && c > rd) skip = true;
    }
    if (!skip) {
        g_parent[c] = rd;
        float w = __uint_as_float((unsigned int)(key >> 32));
        g_edgeW[atomicAdd(&g_cnt, 1)] = w;
    }
}

__global__ void flatten_kernel() {
    int v = blockIdx.x * blockDim.x + threadIdx.x;
    if (v >= N) return;
    int r = g_comp[v];
    while (g_parent[r] != r) r = g_parent[r];
    g_comp[v] = r;
}

// ---------------- 4) sort 2047 weights ascending, write output ----------------
__global__ void sort_out_kernel(float* __restrict__ out) {
    __shared__ float s[N];
    int tid = threadIdx.x;
    for (int i = tid; i < N; i += 1024)
        s[i] = (i < N - 1) ? g_edgeW[i] : 3.4028235e38f;
    __syncthreads();

    for (int k = 2; k <= N; k <<= 1) {
        for (int j = k >> 1; j > 0; j >>= 1) {
            for (int i = tid; i < N; i += 1024) {
                int l = i ^ j;
                if (l > i) {
                    bool up = ((i & k) == 0);
                    float a = s[i], b = s[l];
                    if ((a > b) == up) { s[i] = b; s[l] = a; }
                }
            }
            __syncthreads();
        }
    }
    for (int i = tid; i < N - 1; i += 1024) out[i] = s[i];
}

// ---------------- launch ----------------
extern "C" void kernel_launch(void* const* d_in, const int* in_sizes, int n_in,
                              void* d_out, int out_size) {
    const float* x = (const float*)d_in[0];
    float* out = (float*)d_out;

    sq_kernel<<<N, 128>>>(x);

    dim3 grid(N / 128, N / 128);
    gemm_dist_kernel<<<grid, 256>>>(x);

    init_kernel<<<N / 256, 256>>>();
    for (int r = 0; r < 11; r++) {
        reset_kernel<<<N / 256, 256>>>();
        scan_kernel<<<N, 256>>>();
        merge_kernel<<<N / 256, 256>>>();
        flatten_kernel<<<N / 256, 256>>>();
    }
    sort_out_kernel<<<1, 1024>>>(out);
}

// round 3
// speedup vs baseline: 4.7604x; 4.7604x over previous
#include <cuda_runtime.h>
#include <cuda_bf16.h>
#include <cstdint>
#include <math.h>

#define N 2048
#define K 4096
#define ROUNDS 11
#define STAGES 3
#define BK 64                  // bf16 per chunk = 128B rows
#define CHUNKS (K / BK)        // 64
#define STAGE_BYTES 32768      // A 16KB + B 16KB

// ---------------- device scratch ----------------
__device__ float              g_D[(size_t)N * N];     // 16 MB
__device__ __nv_bfloat16      g_Xb[(size_t)N * K];    // 16 MB
__device__ float              g_sq[N];
__device__ int                g_comp[N];
__device__ int                g_parentR[ROUNDS][N];
__device__ unsigned long long g_minER[ROUNDS][N];
__device__ float              g_edgeW[N];
__device__ int                g_cnt;

// ---------------- helpers ----------------
__device__ __forceinline__ uint32_t s2u(const void* p) {
    return (uint32_t)__cvta_generic_to_shared(p);
}
__device__ __forceinline__ void cp16(uint32_t dst, const void* src) {
    asm volatile("cp.async.cg.shared.global [%0], [%1], 16;" :: "r"(dst), "l"(src) : "memory");
}
__device__ __forceinline__ uint32_t swz(uint32_t off) {
    return off ^ ((off >> 3) & 0x70);
}
__device__ __forceinline__ void ldmx4(uint32_t* r, uint32_t addr) {
    asm volatile("ldmatrix.sync.aligned.m8n8.x4.shared.b16 {%0,%1,%2,%3}, [%4];"
                 : "=r"(r[0]), "=r"(r[1]), "=r"(r[2]), "=r"(r[3]) : "r"(addr));
}
__device__ __forceinline__ void mma16816(float* d, const uint32_t* a, uint32_t b0, uint32_t b1) {
    asm volatile(
        "mma.sync.aligned.m16n8k16.row.col.f32.bf16.bf16.f32 "
        "{%0,%1,%2,%3}, {%4,%5,%6,%7}, {%8,%9}, {%0,%1,%2,%3};"
        : "+f"(d[0]), "+f"(d[1]), "+f"(d[2]), "+f"(d[3])
        : "r"(a[0]), "r"(a[1]), "r"(a[2]), "r"(a[3]), "r"(b0), "r"(b1));
}

// ---------------- 0) fp32 -> bf16 ----------------
__global__ void convert_kernel(const float* __restrict__ x) {
    size_t i = ((size_t)blockIdx.x * 256 + threadIdx.x) * 4;
    float4 v = *(const float4*)(x + i);
    *(__nv_bfloat162*)(g_Xb + i)     = __floats2bfloat162_rn(v.x, v.y);
    *(__nv_bfloat162*)(g_Xb + i + 2) = __floats2bfloat162_rn(v.z, v.w);
}

// ---------------- 1) row squared norms (exact fp32) ----------------
__global__ void sq_kernel(const float* __restrict__ x) {
    int row = blockIdx.x;
    int tid = threadIdx.x;
    const float4* xr = (const float4*)(x + (size_t)row * K);
    float s = 0.f;
    #pragma unroll 4
    for (int i = tid; i < K / 4; i += 128) {
        float4 v = xr[i];
        s += v.x * v.x + v.y * v.y + v.z * v.z + v.w * v.w;
    }
    for (int o = 16; o > 0; o >>= 1) s += __shfl_down_sync(0xffffffffu, s, o);
    __shared__ float ws[4];
    if ((tid & 31) == 0) ws[tid >> 5] = s;
    __syncthreads();
    if (tid == 0) g_sq[row] = ws[0] + ws[1] + ws[2] + ws[3];
}

// ---------------- 2) bf16 HMMA GEMM + distance epilogue ----------------
// BM=BN=128, BK=64, 256 threads (8 warps, 4x2), warp tile 32x64.
// Lower-triangle tiles (bx<=by); mirror written via smem transpose.
__global__ void __launch_bounds__(256, 1) gemm_dist_kernel() {
    extern __shared__ char smem[];
    const int bx = blockIdx.x, by = blockIdx.y;
    if (bx > by) return;

    const int tid  = threadIdx.x;
    const int wid  = tid >> 5;
    const int lane = tid & 31;
    const int wr   = wid >> 1;          // 0..3
    const int wc   = wid & 1;           // 0..1

    uint32_t sb = s2u(smem);
    uint32_t stage_base = (sb + 1023) & ~1023u;

    __shared__ float sqi_s[128], sqj_s[128];

    const __nv_bfloat16* gA = g_Xb + (size_t)(by * 128) * K;
    const __nv_bfloat16* gB = g_Xb + (size_t)(bx * 128) * K;

    auto load_stage = [&](int s, int chunk) {
        uint32_t bA = stage_base + s * STAGE_BYTES;
        uint32_t bB = bA + 16384;
        size_t kb = (size_t)chunk * BK * 2;   // byte offset in a row
        #pragma unroll
        for (int it = 0; it < 4; it++) {
            int q = tid + it * 256;           // 0..1023
            int r = q >> 3, c = q & 7;
            uint32_t sw = swz((uint32_t)(r * 128 + c * 16));
            const char* pa = (const char*)(gA + (size_t)r * K) + kb + c * 16;
            const char* pb = (const char*)(gB + (size_t)r * K) + kb + c * 16;
            cp16(bA + sw, pa);
            cp16(bB + sw, pb);
        }
    };

    float acc[2][8][4];
    #pragma unroll
    for (int i = 0; i < 2; i++)
        #pragma unroll
        for (int j = 0; j < 8; j++)
            #pragma unroll
            for (int c = 0; c < 4; c++) acc[i][j][c] = 0.f;

    // prologue
    load_stage(0, 0);
    asm volatile("cp.async.commit_group;" ::: "memory");
    load_stage(1, 1);
    asm volatile("cp.async.commit_group;" ::: "memory");

    const int rowA0 = wr * 32 + (lane & 15);
    const int rowB0 = wc * 64 + (lane & 15);
    const int hb    = (lane >> 4) * 16;       // k-half byte offset

    for (int c = 0; c < CHUNKS; c++) {
        int s = c % STAGES;
        asm volatile("cp.async.wait_group 1;" ::: "memory");
        __syncthreads();

        if (c + 2 < CHUNKS) load_stage((c + 2) % STAGES, c + 2);
        asm volatile("cp.async.commit_group;" ::: "memory");

        uint32_t bA = stage_base + s * STAGE_BYTES;
        uint32_t bB = bA + 16384;

        #pragma unroll
        for (int kk = 0; kk < 4; kk++) {
            uint32_t a[2][4];
            #pragma unroll
            for (int mi = 0; mi < 2; mi++)
                ldmx4(a[mi], bA + swz((uint32_t)((rowA0 + mi * 16) * 128 + kk * 32 + hb)));
            uint32_t b[4][4];
            #pragma unroll
            for (int nb = 0; nb < 4; nb++)
                ldmx4(b[nb], bB + swz((uint32_t)((rowB0 + nb * 16) * 128 + kk * 32 + hb)));
            #pragma unroll
            for (int mi = 0; mi < 2; mi++)
                #pragma unroll
                for (int nb = 0; nb < 4; nb++) {
                    mma16816(acc[mi][nb * 2],     a[mi], b[nb][0], b[nb][2]);
                    mma16816(acc[mi][nb * 2 + 1], a[mi], b[nb][1], b[nb][3]);
                }
        }
    }

    // epilogue
    if (tid < 128) {
        sqi_s[tid] = g_sq[by * 128 + tid];
        sqj_s[tid] = g_sq[bx * 128 + tid];
    }
    __syncthreads();   // also guards smem reuse below

    float* tbuf = (float*)(smem + (stage_base - sb));   // 128 x 129 fp32

    #pragma unroll
    for (int mi = 0; mi < 2; mi++)
        #pragma unroll
        for (int ni = 0; ni < 8; ni++)
            #pragma unroll
            for (int cc = 0; cc < 4; cc++) {
                int row = wr * 32 + mi * 16 + (lane >> 2) + ((cc >> 1) * 8);
                int col = wc * 64 + ni * 8 + (lane & 3) * 2 + (cc & 1);
                float d2 = sqi_s[row] + sqj_s[col] - 2.f * acc[mi][ni][cc];
                tbuf[row * 129 + col] = sqrtf(fmaxf(d2, 0.f));
            }
    __syncthreads();

    int col = tid & 127, r0 = tid >> 7;
    for (int rr = r0; rr < 128; rr += 2)
        g_D[(size_t)(by * 128 + rr) * N + bx * 128 + col] = tbuf[rr * 129 + col];
    if (bx != by)
        for (int rr = r0; rr < 128; rr += 2)
            g_D[(size_t)(bx * 128 + rr) * N + by * 128 + col] = tbuf[col * 129 + rr];
}

// ---------------- 3) Boruvka MST ----------------
__global__ void init_kernel() {
    int i = blockIdx.x * blockDim.x + threadIdx.x;
    if (i < N) g_comp[i] = i;
    if (i == 0) g_cnt = 0;
    if (i < ROUNDS * N) {
        ((unsigned long long*)g_minER)[i] = ~0ull;
        ((int*)g_parentR)[i] = i % N;
    }
}

__global__ void scan_kernel(int round) {
    __shared__ int scomp[N];
    __shared__ unsigned long long sm[256];
    int v = blockIdx.x;
    int tid = threadIdx.x;
    for (int j = tid; j < N; j += 256) scomp[j] = g_comp[j];
    __syncthreads();
    int cv = scomp[v];
    const float* __restrict__ row = g_D + (size_t)v * N;

    unsigned long long best = ~0ull;
    for (int j = tid; j < N; j += 256) {
        if (scomp[j] != cv) {
            float w = row[j];
            unsigned int p = (v < j) ? (unsigned)(v * N + j) : (unsigned)(j * N + v);
            unsigned long long key = ((unsigned long long)__float_as_uint(w) << 32) | p;
            best = min(best, key);
        }
    }
    sm[tid] = best;
    __syncthreads();
    for (int s = 128; s > 0; s >>= 1) {
        if (tid < s) sm[tid] = min(sm[tid], sm[tid + s]);
        __syncthreads();
    }
    if (tid == 0 && sm[0] != ~0ull) atomicMin(&g_minER[round][cv], sm[0]);
}

__global__ void merge_kernel(int round) {
    int c = blockIdx.x * blockDim.x + threadIdx.x;
    if (c >= N || g_comp[c] != c) return;
    unsigned long long key = g_minER[round][c];
    if (key == ~0ull) return;

    unsigned int p = (unsigned int)key;
    int a = p / N, b = p % N;
    int ra = g_comp[a], rb = g_comp[b];
    int rd = (ra == c) ? rb : ra;

    bool skip = false;
    unsigned long long key2 = g_minER[round][rd];
    if (key2 != ~0ull) {
        unsigned int p2 = (unsigned int)key2;
        int a2 = p2 / N, b2 = p2 % N;
        int ra2 = g_comp[a2], rb2 = g_comp[b2];
        int tgt = (ra2 == rd) ? rb2 : ra2;
        if (tgt == c && c > rd) skip = true;
    }
    if (!skip) {
        g_parentR[round][c] = rd;
        float w = __uint_as_float((unsigned int)(key >> 32));
        g_edgeW[atomicAdd(&g_cnt, 1)] = w;
    }
}

__global__ void flatten_kernel(int round) {
    int v = blockIdx.x * blockDim.x + threadIdx.x;
    if (v >= N) return;
    int r = g_comp[v];
    while (g_parentR[round][r] != r) r = g_parentR[round][r];
    g_comp[v] = r;
}

// ---------------- 4) bitonic sort, write output ----------------
__global__ void sort_out_kernel(float* __restrict__ out) {
    __shared__ float s[N];
    int tid = threadIdx.x;
    for (int i = tid; i < N; i += 1024)
        s[i] = (i < N - 1) ? g_edgeW[i] : 3.4028235e38f;
    __syncthreads();
    for (int k = 2; k <= N; k <<= 1) {
        for (int j = k >> 1; j > 0; j >>= 1) {
            for (int i = tid; i < N; i += 1024) {
                int l = i ^ j;
                if (l > i) {
                    bool up = ((i & k) == 0);
                    float a = s[i], b = s[l];
                    if ((a > b) == up) { s[i] = b; s[l] = a; }
                }
            }
            __syncthreads();
        }
    }
    for (int i = tid; i < N - 1; i += 1024) out[i] = s[i];
}

// ---------------- launch ----------------
extern "C" void kernel_launch(void* const* d_in, const int* in_sizes, int n_in,
                              void* d_out, int out_size) {
    const float* x = (const float*)d_in[0];
    float* out = (float*)d_out;

    convert_kernel<<<(N * K) / (256 * 4), 256>>>(x);
    sq_kernel<<<N, 128>>>(x);

    static const int SMEM_SZ = STAGES * STAGE_BYTES + 1024;
    cudaFuncSetAttribute(gemm_dist_kernel,
                         cudaFuncAttributeMaxDynamicSharedMemorySize, SMEM_SZ);
    gemm_dist_kernel<<<dim3(16, 16), 256, SMEM_SZ>>>();

    init_kernel<<<(ROUNDS * N + 255) / 256, 256>>>();
    for (int r = 0; r < ROUNDS; r++) {
        scan_kernel<<<N, 256>>>(r);
        merge_kernel<<<N / 256, 256>>>(r);
        flatten_kernel<<<N / 256, 256>>>(r);
    }
    sort_out_kernel<<<1, 1024>>>(out);
}